// round 4
// baseline (speedup 1.0000x reference)
#include <cuda_runtime.h>

// ---------------------------------------------------------------------------
// SCM_MLP: 4 chained layers of  out = relu(out @ (W*mask)^T + exp(mu+sigma*z))
// with per-layer activations concatenated into d_out [B, 4*H].
//
// Strategy (round 1): fp32 SGEMM on CUDA cores using packed fma.rn.f32x2
// (FFMA2: 2x the FFMA rate; ptxas never emits it from C++ so we inline PTX),
// mask pre-multiplied into a __device__ scratch, noise+relu fused in the
// GEMM epilogue, layer chaining through d_out itself (ld = 4*H).
// ---------------------------------------------------------------------------

static constexpr int NL = 4;
static constexpr int NB = 4096;   // batch
static constexpr int NH = 4096;   // hidden
static constexpr int BM = 128;
static constexpr int BN = 128;
static constexpr int BK = 16;
static constexpr int THREADS = 256;

// Masked-weight scratch: 4 * 4096 * 4096 floats = 256 MiB (module-load alloc,
// the sanctioned workaround for no-cudaMalloc).
__device__ float g_wm[(size_t)NL * NH * NH];

// ---------------------------------------------------------------------------
// Prepass: Wm = W * mask, float4-vectorized.
// ---------------------------------------------------------------------------
__global__ void maskmul_kernel(const float* __restrict__ w,
                               const float* __restrict__ m) {
    size_t i = (size_t)blockIdx.x * blockDim.x + threadIdx.x;  // float4 index
    float4 a = ((const float4*)w)[i];
    float4 b = ((const float4*)m)[i];
    float4 r;
    r.x = a.x * b.x; r.y = a.y * b.y; r.z = a.z * b.z; r.w = a.w * b.w;
    ((float4*)g_wm)[i] = r;
}

// ---------------------------------------------------------------------------
// Fused GEMM + lognormal-noise + ReLU.
//   C[b, o] = relu( sum_i A[b,i] * Wm[o,i] + exp(mu[o] + sigma[o]*z[b,o]) )
// A: [M, K] row-major with leading dim lda (x for layer 0, d_out slice after).
// Wm: [N, K] row-major (K contiguous) -> classic NT GEMM.
// C: pre-offset to out + l*H, row stride 4*H.
// ---------------------------------------------------------------------------
__global__ void __launch_bounds__(THREADS, 2)
gemm_fused_kernel(const float* __restrict__ A, int lda, int layer,
                  const float* __restrict__ z,
                  const float* __restrict__ mu,
                  const float* __restrict__ sig,
                  float* __restrict__ C) {
    __shared__ float As[BK][BM];
    __shared__ float Bs[BK][BN];

    const float* Wm = g_wm + (size_t)layer * NH * NH;

    const int t  = threadIdx.x;
    const int m0 = blockIdx.y * BM;
    const int n0 = blockIdx.x * BN;
    const int tx = t & 15;          // 16 col groups
    const int ty = t >> 4;          // 16 row groups
    const int rm = ty * 8;          // this thread's 8 rows within tile
    const int cn = tx * 8;          // this thread's 8 cols within tile

    // Global->smem load decomposition: 512 float4 per 128x16 tile, 2/thread.
    const int r0  = t >> 2;                 // rows 0..63
    const int r1  = r0 + 64;                // rows 64..127
    const int kc  = (t & 3) << 2;           // k-offset within tile (0,4,8,12)

    const float* Ag0 = A  + (size_t)(m0 + r0) * lda + kc;
    const float* Ag1 = A  + (size_t)(m0 + r1) * lda + kc;
    const float* Bg0 = Wm + (size_t)(n0 + r0) * NH  + kc;
    const float* Bg1 = Wm + (size_t)(n0 + r1) * NH  + kc;

    // 8x8 accumulator as 8x4 packed f32x2 pairs (pairs along N).
    unsigned long long acc[8][4];
#pragma unroll
    for (int i = 0; i < 8; i++)
#pragma unroll
        for (int j = 0; j < 4; j++) acc[i][j] = 0ull;

    float4 sA0, sA1, sB0, sB1;

#define SCATTER_TILE()                                                        \
    do {                                                                      \
        As[kc + 0][r0] = sA0.x; As[kc + 1][r0] = sA0.y;                       \
        As[kc + 2][r0] = sA0.z; As[kc + 3][r0] = sA0.w;                       \
        As[kc + 0][r1] = sA1.x; As[kc + 1][r1] = sA1.y;                       \
        As[kc + 2][r1] = sA1.z; As[kc + 3][r1] = sA1.w;                       \
        Bs[kc + 0][r0] = sB0.x; Bs[kc + 1][r0] = sB0.y;                       \
        Bs[kc + 2][r0] = sB0.z; Bs[kc + 3][r0] = sB0.w;                       \
        Bs[kc + 0][r1] = sB1.x; Bs[kc + 1][r1] = sB1.y;                       \
        Bs[kc + 2][r1] = sB1.z; Bs[kc + 3][r1] = sB1.w;                       \
    } while (0)

    // Prologue: tile 0
    sA0 = *(const float4*)(Ag0);
    sA1 = *(const float4*)(Ag1);
    sB0 = *(const float4*)(Bg0);
    sB1 = *(const float4*)(Bg1);
    SCATTER_TILE();
    __syncthreads();

    const int NKT = NH / BK;  // 256 k-tiles
    for (int kt = 0; kt < NKT; kt++) {
        const bool more = (kt + 1 < NKT);
        if (more) {
            const int off = (kt + 1) * BK;  // floats
            sA0 = *(const float4*)(Ag0 + off);
            sA1 = *(const float4*)(Ag1 + off);
            sB0 = *(const float4*)(Bg0 + off);
            sB1 = *(const float4*)(Bg1 + off);
        }

#pragma unroll
        for (int k = 0; k < BK; k++) {
            float4 a0 = *(const float4*)&As[k][rm];
            float4 a1 = *(const float4*)&As[k][rm + 4];
            ulonglong2 q0 = *(const ulonglong2*)&Bs[k][cn];
            ulonglong2 q1 = *(const ulonglong2*)&Bs[k][cn + 4];
            float av[8] = {a0.x, a0.y, a0.z, a0.w, a1.x, a1.y, a1.z, a1.w};
#pragma unroll
            for (int i = 0; i < 8; i++) {
                unsigned long long aa;
                asm("mov.b64 %0, {%1, %1};" : "=l"(aa) : "f"(av[i]));
                asm("fma.rn.f32x2 %0, %1, %2, %0;"
                    : "+l"(acc[i][0]) : "l"(aa), "l"(q0.x));
                asm("fma.rn.f32x2 %0, %1, %2, %0;"
                    : "+l"(acc[i][1]) : "l"(aa), "l"(q0.y));
                asm("fma.rn.f32x2 %0, %1, %2, %0;"
                    : "+l"(acc[i][2]) : "l"(aa), "l"(q1.x));
                asm("fma.rn.f32x2 %0, %1, %2, %0;"
                    : "+l"(acc[i][3]) : "l"(aa), "l"(q1.y));
            }
        }

        if (more) {
            __syncthreads();
            SCATTER_TILE();
            __syncthreads();
        }
    }

    // ---------------- epilogue: noise + relu + store ----------------
    const int go = n0 + cn;
    float4 mu0 = *(const float4*)(mu + go);
    float4 mu1 = *(const float4*)(mu + go + 4);
    float4 sg0 = *(const float4*)(sig + go);
    float4 sg1 = *(const float4*)(sig + go + 4);
    float muv[8] = {mu0.x, mu0.y, mu0.z, mu0.w, mu1.x, mu1.y, mu1.z, mu1.w};
    float sgv[8] = {sg0.x, sg0.y, sg0.z, sg0.w, sg1.x, sg1.y, sg1.z, sg1.w};

#pragma unroll
    for (int i = 0; i < 8; i++) {
        const int gb = m0 + rm + i;
        const float* zr = z + (size_t)gb * NH + go;
        float4 zv0 = *(const float4*)(zr);
        float4 zv1 = *(const float4*)(zr + 4);
        float zz[8] = {zv0.x, zv0.y, zv0.z, zv0.w, zv1.x, zv1.y, zv1.z, zv1.w};

        float res[8];
#pragma unroll
        for (int j = 0; j < 4; j++) {
            float lo, hi;
            asm("mov.b64 {%0, %1}, %2;" : "=f"(lo), "=f"(hi) : "l"(acc[i][j]));
            res[2 * j]     = lo;
            res[2 * j + 1] = hi;
        }
#pragma unroll
        for (int u = 0; u < 8; u++) {
            float noise = __expf(fmaf(sgv[u], zz[u], muv[u]));
            res[u] = fmaxf(res[u] + noise, 0.0f);
        }

        float* cr = C + (size_t)gb * (4 * NH) + go;
        float4 o0; o0.x = res[0]; o0.y = res[1]; o0.z = res[2]; o0.w = res[3];
        float4 o1; o1.x = res[4]; o1.y = res[5]; o1.z = res[6]; o1.w = res[7];
        *(float4*)(cr)     = o0;
        *(float4*)(cr + 4) = o1;
    }
#undef SCATTER_TILE
}

// ---------------------------------------------------------------------------
// kernel_launch: 1 prepass + 4 chained fused GEMMs, all graph-capturable.
// Input order (metadata): x, weights, masks, mu, sigma, z. Output: float32.
// ---------------------------------------------------------------------------
extern "C" void kernel_launch(void* const* d_in, const int* in_sizes, int n_in,
                              void* d_out, int out_size) {
    const float* x   = (const float*)d_in[0];  // [B, H]
    const float* w   = (const float*)d_in[1];  // [L, H, H]
    const float* mk  = (const float*)d_in[2];  // [L, H, H]
    const float* mu  = (const float*)d_in[3];  // [L, H]
    const float* sg  = (const float*)d_in[4];  // [L, H]
    const float* z   = (const float*)d_in[5];  // [L, B, H]
    float*       out = (float*)d_out;          // [B, L*H]

    // Prepass: Wm = W * mask  (L*H*H / 4 float4 elements)
    const size_t n4 = (size_t)NL * NH * NH / 4;
    maskmul_kernel<<<(unsigned)(n4 / THREADS), THREADS>>>(w, mk);

    dim3 grid(NH / BN, NB / BM);  // (32, 32)
    for (int l = 0; l < NL; l++) {
        const float* Ap  = (l == 0) ? x : (out + (size_t)(l - 1) * NH);
        const int    lda = (l == 0) ? NH : 4 * NH;
        gemm_fused_kernel<<<grid, THREADS>>>(
            Ap, lda, l,
            z + (size_t)l * NB * NH,
            mu + (size_t)l * NH,
            sg + (size_t)l * NH,
            out + (size_t)l * NH);
    }
}

// round 6
// speedup vs baseline: 1.8636x; 1.8636x over previous
#include <cuda_runtime.h>
#include <cuda_bf16.h>
#include <mma.h>
#include <cstdint>

using namespace nvcuda;

// ---------------------------------------------------------------------------
// SCM_MLP: 4 chained layers  out = relu(out @ (W*mask)^T + exp(mu+sig*z)),
// activations concatenated into d_out [B, 4H].
//
// Tensor-core route that survives the compute_103 (family-generic) target:
// wmma/mma.sync bf16 m16n8k16 (sm_80+ ISA), 3-term Markidis split
//   A*W ~= Ahi*Whi + Ahi*Wlo + Alo*Whi  (fp32 accumulate)
// cp.async 3-stage pipeline, fused noise+relu epilogue that also emits the
// next layer's bf16 hi/lo activation scratch.
// ---------------------------------------------------------------------------

static constexpr int NL = 4, NB = 4096, NH = 4096;
static constexpr int BM = 128, BN = 128, BK = 32, STAGES = 3;
static constexpr int NKT = NH / BK;            // 128 k-tiles
static constexpr int LDSR = 40;                // smem row stride in bf16 (80 B)
static constexpr int TILE_E  = 128 * LDSR;     // 5120 bf16 per tile
static constexpr int STAGE_E = 4 * TILE_E;     // Ahi,Alo,Whi,Wlo
static constexpr int SMEM_BYTES = STAGES * STAGE_E * 2;  // 122880
static constexpr int FB_LD = 132;              // fp32 epilogue buffer stride

// ------------------------- device scratch (.bss) ---------------------------
__device__ char g_whi[(size_t)NL * NH * NH * 2];   // 128 MiB bf16 hi
__device__ char g_wlo[(size_t)NL * NH * NH * 2];   // 128 MiB bf16 lo
__device__ char g_ahi[2][(size_t)NB * NH * 2];     // ping-pong activations hi
__device__ char g_alo[2][(size_t)NB * NH * 2];     // ping-pong activations lo

// ------------------------------ helpers ------------------------------------
__device__ __forceinline__ void cp16(void* s, const void* g) {
    uint32_t sa = (uint32_t)__cvta_generic_to_shared(s);
    asm volatile("cp.async.cg.shared.global [%0], [%1], 16;" :: "r"(sa), "l"(g));
}
#define CP_COMMIT() asm volatile("cp.async.commit_group;" ::: "memory")
#define CP_WAIT1()  asm volatile("cp.async.wait_group 1;" ::: "memory")

__device__ __forceinline__ uint32_t pack2(__nv_bfloat16 a, __nv_bfloat16 b) {
    __nv_bfloat162 t(a, b);
    return *reinterpret_cast<uint32_t*>(&t);
}

// ---------------------------------------------------------------------------
// Prepass: split W*mask into bf16 hi/lo (row-major, same [L][N][K] layout).
// ---------------------------------------------------------------------------
__global__ void wsplit_kernel(const float* __restrict__ w, const float* __restrict__ m) {
    size_t e = ((size_t)blockIdx.x * 256u + threadIdx.x) * 2u;
    float2 wv = *(const float2*)(w + e);
    float2 mv = *(const float2*)(m + e);
    float v0 = wv.x * mv.x, v1 = wv.y * mv.y;
    __nv_bfloat16 h0 = __float2bfloat16(v0), h1 = __float2bfloat16(v1);
    float l0 = v0 - __bfloat162float(h0), l1 = v1 - __bfloat162float(h1);
    *(uint32_t*)(g_whi + e * 2) = pack2(h0, h1);
    *(uint32_t*)(g_wlo + e * 2) = pack2(__float2bfloat16(l0), __float2bfloat16(l1));
}

// Prepass: split x into bf16 hi/lo (buffer 0).
__global__ void xsplit_kernel(const float* __restrict__ x) {
    size_t e = ((size_t)blockIdx.x * 256u + threadIdx.x) * 2u;
    float2 xv = *(const float2*)(x + e);
    __nv_bfloat16 h0 = __float2bfloat16(xv.x), h1 = __float2bfloat16(xv.y);
    float l0 = xv.x - __bfloat162float(h0), l1 = xv.y - __bfloat162float(h1);
    *(uint32_t*)(g_ahi[0] + e * 2) = pack2(h0, h1);
    *(uint32_t*)(g_alo[0] + e * 2) = pack2(__float2bfloat16(l0), __float2bfloat16(l1));
}

// ---------------------------------------------------------------------------
// Fused wmma GEMM + noise + relu + next-layer split.
// grid (32, 32): n0 = bx*128, m0 = by*128. 256 threads, 8 warps of 64x32.
// ---------------------------------------------------------------------------
__global__ void __launch_bounds__(256, 1)
gemm_tc_kernel(int layer, int abuf, int last,
               const float* __restrict__ z, const float* __restrict__ mu,
               const float* __restrict__ sig, float* __restrict__ out) {
    extern __shared__ __nv_bfloat16 smem[];
    const int tid = threadIdx.x;
    const int wid = tid >> 5;
    const int wm = wid >> 2;          // 0..1  (warp row: 64 rows)
    const int wn = wid & 3;           // 0..3  (warp col: 32 cols)
    const int n0 = blockIdx.x * BN;
    const int m0 = blockIdx.y * BM;

    // Global tile bases (bytes), row stride NH*2.
    const char* src[4];
    src[0] = g_ahi[abuf] + (size_t)m0 * NH * 2;
    src[1] = g_alo[abuf] + (size_t)m0 * NH * 2;
    src[2] = g_whi + ((size_t)layer * NH + n0) * NH * 2;
    src[3] = g_wlo + ((size_t)layer * NH + n0) * NH * 2;

    // Per-thread load slots: 512 16B-chunks per tile, 2 per thread per tile.
    const int r_0 = tid >> 2,        c_0 = tid & 3;           // idx = tid
    const int r_1 = (tid + 256) >> 2, c_1 = (tid + 256) & 3;  // idx = tid+256

    auto load_stage = [&](int slot, int kt) {
        __nv_bfloat16* st = smem + slot * STAGE_E;
        const size_t kb = (size_t)kt * 64;  // byte offset along K
#pragma unroll
        for (int t = 0; t < 4; t++) {
            cp16(st + t * TILE_E + r_0 * LDSR + c_0 * 8,
                 src[t] + (size_t)r_0 * (NH * 2) + kb + c_0 * 16);
            cp16(st + t * TILE_E + r_1 * LDSR + c_1 * 8,
                 src[t] + (size_t)r_1 * (NH * 2) + kb + c_1 * 16);
        }
    };

    wmma::fragment<wmma::accumulator, 16, 16, 16, float> acc[4][2];
#pragma unroll
    for (int i = 0; i < 4; i++)
#pragma unroll
        for (int j = 0; j < 2; j++) wmma::fill_fragment(acc[i][j], 0.0f);

    // Prologue: stages 0, 1.
    load_stage(0, 0); CP_COMMIT();
    load_stage(1, 1); CP_COMMIT();

    for (int kt = 0; kt < NKT; kt++) {
        CP_WAIT1();
        __syncthreads();
        if (kt + 2 < NKT) load_stage((kt + 2) % STAGES, kt + 2);
        CP_COMMIT();

        const __nv_bfloat16* st = smem + (kt % STAGES) * STAGE_E;
        const __nv_bfloat16* sAh = st;
        const __nv_bfloat16* sAl = st + TILE_E;
        const __nv_bfloat16* sWh = st + 2 * TILE_E;
        const __nv_bfloat16* sWl = st + 3 * TILE_E;

#pragma unroll
        for (int ks = 0; ks < 2; ks++) {
            wmma::fragment<wmma::matrix_a, 16, 16, 16, __nv_bfloat16, wmma::row_major> aH[4], aL[4];
            wmma::fragment<wmma::matrix_b, 16, 16, 16, __nv_bfloat16, wmma::col_major> bH[2], bL[2];
#pragma unroll
            for (int i = 0; i < 4; i++) {
                const int ro = (wm * 64 + i * 16) * LDSR + ks * 16;
                wmma::load_matrix_sync(aH[i], sAh + ro, LDSR);
                wmma::load_matrix_sync(aL[i], sAl + ro, LDSR);
            }
#pragma unroll
            for (int j = 0; j < 2; j++) {
                const int ro = (wn * 32 + j * 16) * LDSR + ks * 16;
                wmma::load_matrix_sync(bH[j], sWh + ro, LDSR);
                wmma::load_matrix_sync(bL[j], sWl + ro, LDSR);
            }
#pragma unroll
            for (int i = 0; i < 4; i++)
#pragma unroll
                for (int j = 0; j < 2; j++) {
                    wmma::mma_sync(acc[i][j], aH[i], bH[j], acc[i][j]);
                    wmma::mma_sync(acc[i][j], aH[i], bL[j], acc[i][j]);
                    wmma::mma_sync(acc[i][j], aL[i], bH[j], acc[i][j]);
                }
        }
        __syncthreads();
    }

    // ------------------------- epilogue ------------------------------------
    float* fb = (float*)smem;   // 128 x FB_LD fp32 (67.6 KB, reuses stages)
#pragma unroll
    for (int i = 0; i < 4; i++)
#pragma unroll
        for (int j = 0; j < 2; j++)
            wmma::store_matrix_sync(fb + (wm * 64 + i * 16) * FB_LD + wn * 32 + j * 16,
                                    acc[i][j], FB_LD, wmma::mem_row_major);
    __syncthreads();

    const float* zb = z + (size_t)m0 * NH + n0;
    float* ob = out + (size_t)m0 * (4 * NH) + n0;
    char* nxH = g_ahi[abuf ^ 1];
    char* nxL = g_alo[abuf ^ 1];

#pragma unroll
    for (int it = 0; it < 16; it++) {
        int idx4 = tid + it * 256;            // 0..4095 float4 slots
        int row  = idx4 >> 5;                 // 0..127
        int c4   = (idx4 & 31) << 2;          // 0..124

        float4 a  = *(float4*)&fb[row * FB_LD + c4];
        float4 zv = *(const float4*)(zb + (size_t)row * NH + c4);
        float4 mv = *(const float4*)(mu + n0 + c4);
        float4 sv = *(const float4*)(sig + n0 + c4);

        float v0 = fmaxf(a.x + __expf(fmaf(sv.x, zv.x, mv.x)), 0.0f);
        float v1 = fmaxf(a.y + __expf(fmaf(sv.y, zv.y, mv.y)), 0.0f);
        float v2 = fmaxf(a.z + __expf(fmaf(sv.z, zv.z, mv.z)), 0.0f);
        float v3 = fmaxf(a.w + __expf(fmaf(sv.w, zv.w, mv.w)), 0.0f);

        float4 o; o.x = v0; o.y = v1; o.z = v2; o.w = v3;
        *(float4*)(ob + (size_t)row * (4 * NH) + c4) = o;

        if (!last) {
            __nv_bfloat16 h0 = __float2bfloat16(v0), h1 = __float2bfloat16(v1);
            __nv_bfloat16 h2 = __float2bfloat16(v2), h3 = __float2bfloat16(v3);
            float l0 = v0 - __bfloat162float(h0), l1 = v1 - __bfloat162float(h1);
            float l2 = v2 - __bfloat162float(h2), l3 = v3 - __bfloat162float(h3);
            size_t off = ((size_t)(m0 + row) * NH + n0 + c4) * 2;  // bytes
            uint2 ph; ph.x = pack2(h0, h1); ph.y = pack2(h2, h3);
            uint2 pl; pl.x = pack2(__float2bfloat16(l0), __float2bfloat16(l1));
            pl.y = pack2(__float2bfloat16(l2), __float2bfloat16(l3));
            *(uint2*)(nxH + off) = ph;
            *(uint2*)(nxL + off) = pl;
        }
    }
}

// ---------------------------------------------------------------------------
// kernel_launch: prepasses + 4 chained fused GEMMs, graph-capturable.
// Inputs: x, weights, masks, mu, sigma, z. Output float32 [B, 4H].
// ---------------------------------------------------------------------------
extern "C" void kernel_launch(void* const* d_in, const int* in_sizes, int n_in,
                              void* d_out, int out_size) {
    const float* x   = (const float*)d_in[0];
    const float* w   = (const float*)d_in[1];
    const float* mk  = (const float*)d_in[2];
    const float* mu  = (const float*)d_in[3];
    const float* sg  = (const float*)d_in[4];
    const float* z   = (const float*)d_in[5];
    float*       out = (float*)d_out;

    cudaFuncSetAttribute(gemm_tc_kernel,
                         cudaFuncAttributeMaxDynamicSharedMemorySize, SMEM_BYTES);

    {   // W split: NL*NH*NH/2 bf16-pairs
        unsigned blocks = (unsigned)(((size_t)NL * NH * NH / 2) / 256);
        wsplit_kernel<<<blocks, 256>>>(w, mk);
    }
    {   // x split
        unsigned blocks = (unsigned)(((size_t)NB * NH / 2) / 256);
        xsplit_kernel<<<blocks, 256>>>(x);
    }

    dim3 grid(NH / BN, NB / BM);  // (32, 32)
    for (int l = 0; l < NL; l++) {
        gemm_tc_kernel<<<grid, 256, SMEM_BYTES>>>(
            l, l & 1, (l == NL - 1) ? 1 : 0,
            z + (size_t)l * NB * NH,
            mu + (size_t)l * NH,
            sg + (size_t)l * NH,
            out + (size_t)l * NH);
    }
}

// round 8
// speedup vs baseline: 2.4273x; 1.3025x over previous
#include <cuda_runtime.h>
#include <cuda_bf16.h>
#include <mma.h>
#include <cstdint>

using namespace nvcuda;

// ---------------------------------------------------------------------------
// SCM_MLP: 4 chained layers  out = relu(out @ (W*mask)^T + exp(mu+sig*z)),
// activations concatenated into d_out [B, 4H].
//
// wmma/mma.sync bf16 (family-generic ISA, survives compute_103 target),
// 3-term Markidis split  A*W ~= Ahi*Whi + Ahi*Wlo + Alo*Whi, fp32 accum.
// R8: 2-stage cp.async pipeline (80 KB) + __launch_bounds__(256,2) => two
// CTAs per SM; CP_COMMIT made unconditional so wait_group 1 always retires
// the current tile's group (R7 had it guarded -> last tile raced).
// ---------------------------------------------------------------------------

static constexpr int NL = 4, NB = 4096, NH = 4096;
static constexpr int BM = 128, BN = 128, BK = 32, STAGES = 2;
static constexpr int NKT = NH / BK;            // 128 k-tiles
static constexpr int LDSR = 40;                // smem row stride in bf16 (80 B)
static constexpr int TILE_E  = 128 * LDSR;     // 5120 bf16 per tile
static constexpr int STAGE_E = 4 * TILE_E;     // Ahi,Alo,Whi,Wlo
static constexpr int SMEM_BYTES = STAGES * STAGE_E * 2;  // 81920
static constexpr int FB_LD = 132;              // fp32 epilogue buffer stride

// ------------------------- device scratch (.bss) ---------------------------
__device__ char g_whi[(size_t)NL * NH * NH * 2];   // 128 MiB bf16 hi
__device__ char g_wlo[(size_t)NL * NH * NH * 2];   // 128 MiB bf16 lo
__device__ char g_ahi[2][(size_t)NB * NH * 2];     // ping-pong activations hi
__device__ char g_alo[2][(size_t)NB * NH * 2];     // ping-pong activations lo

// ------------------------------ helpers ------------------------------------
__device__ __forceinline__ void cp16(void* s, const void* g) {
    uint32_t sa = (uint32_t)__cvta_generic_to_shared(s);
    asm volatile("cp.async.cg.shared.global [%0], [%1], 16;" :: "r"(sa), "l"(g));
}
#define CP_COMMIT() asm volatile("cp.async.commit_group;" ::: "memory")
#define CP_WAIT1()  asm volatile("cp.async.wait_group 1;" ::: "memory")

__device__ __forceinline__ uint32_t pack2(__nv_bfloat16 a, __nv_bfloat16 b) {
    __nv_bfloat162 t(a, b);
    return *reinterpret_cast<uint32_t*>(&t);
}

// ---------------------------------------------------------------------------
// Prepass: split W*mask into bf16 hi/lo (row-major [L][N][K]).
// ---------------------------------------------------------------------------
__global__ void wsplit_kernel(const float* __restrict__ w, const float* __restrict__ m) {
    size_t e = ((size_t)blockIdx.x * 256u + threadIdx.x) * 2u;
    float2 wv = *(const float2*)(w + e);
    float2 mv = *(const float2*)(m + e);
    float v0 = wv.x * mv.x, v1 = wv.y * mv.y;
    __nv_bfloat16 h0 = __float2bfloat16(v0), h1 = __float2bfloat16(v1);
    float l0 = v0 - __bfloat162float(h0), l1 = v1 - __bfloat162float(h1);
    *(uint32_t*)(g_whi + e * 2) = pack2(h0, h1);
    *(uint32_t*)(g_wlo + e * 2) = pack2(__float2bfloat16(l0), __float2bfloat16(l1));
}

// Prepass: split x into bf16 hi/lo (buffer 0).
__global__ void xsplit_kernel(const float* __restrict__ x) {
    size_t e = ((size_t)blockIdx.x * 256u + threadIdx.x) * 2u;
    float2 xv = *(const float2*)(x + e);
    __nv_bfloat16 h0 = __float2bfloat16(xv.x), h1 = __float2bfloat16(xv.y);
    float l0 = xv.x - __bfloat162float(h0), l1 = xv.y - __bfloat162float(h1);
    *(uint32_t*)(g_ahi[0] + e * 2) = pack2(h0, h1);
    *(uint32_t*)(g_alo[0] + e * 2) = pack2(__float2bfloat16(l0), __float2bfloat16(l1));
}

// ---------------------------------------------------------------------------
// Fused wmma GEMM + noise + relu + next-layer split.
// grid (32, 32): n0 = bx*128, m0 = by*128. 256 threads, 8 warps of 64x32.
// ---------------------------------------------------------------------------
__global__ void __launch_bounds__(256, 2)
gemm_tc_kernel(int layer, int abuf, int last,
               const float* __restrict__ z, const float* __restrict__ mu,
               const float* __restrict__ sig, float* __restrict__ out) {
    extern __shared__ __nv_bfloat16 smem[];
    const int tid = threadIdx.x;
    const int wid = tid >> 5;
    const int wm = wid >> 2;          // 0..1  (warp row: 64 rows)
    const int wn = wid & 3;           // 0..3  (warp col: 32 cols)
    const int n0 = blockIdx.x * BN;
    const int m0 = blockIdx.y * BM;

    const char* src[4];
    src[0] = g_ahi[abuf] + (size_t)m0 * NH * 2;
    src[1] = g_alo[abuf] + (size_t)m0 * NH * 2;
    src[2] = g_whi + ((size_t)layer * NH + n0) * NH * 2;
    src[3] = g_wlo + ((size_t)layer * NH + n0) * NH * 2;

    // Per-thread load slots: 512 16B-chunks per tile, 2 per thread per tile.
    const int r_0 = tid >> 2,         c_0 = tid & 3;
    const int r_1 = (tid + 256) >> 2, c_1 = (tid + 256) & 3;

    auto load_stage = [&](int slot, int kt) {
        __nv_bfloat16* st = smem + slot * STAGE_E;
        const size_t kb = (size_t)kt * 64;  // byte offset along K
#pragma unroll
        for (int t = 0; t < 4; t++) {
            cp16(st + t * TILE_E + r_0 * LDSR + c_0 * 8,
                 src[t] + (size_t)r_0 * (NH * 2) + kb + c_0 * 16);
            cp16(st + t * TILE_E + r_1 * LDSR + c_1 * 8,
                 src[t] + (size_t)r_1 * (NH * 2) + kb + c_1 * 16);
        }
    };

    wmma::fragment<wmma::accumulator, 16, 16, 16, float> acc[4][2];
#pragma unroll
    for (int i = 0; i < 4; i++)
#pragma unroll
        for (int j = 0; j < 2; j++) wmma::fill_fragment(acc[i][j], 0.0f);

    // Prologue: stage 0.
    load_stage(0, 0); CP_COMMIT();

    for (int kt = 0; kt < NKT; kt++) {
        // Prefetch kt+1 into the other buffer; that buffer was last consumed
        // in iteration kt-1 and all warps passed kt-1's closing barrier.
        if (kt + 1 < NKT) load_stage((kt + 1) & 1, kt + 1);
        CP_COMMIT();                   // unconditional: group exists even when
                                       // empty, so WAIT1 retires group kt.
        CP_WAIT1();                    // stage kt resident; kt+1 may be in flight
        __syncthreads();

        const __nv_bfloat16* st = smem + (kt & 1) * STAGE_E;
        const __nv_bfloat16* sAh = st;
        const __nv_bfloat16* sAl = st + TILE_E;
        const __nv_bfloat16* sWh = st + 2 * TILE_E;
        const __nv_bfloat16* sWl = st + 3 * TILE_E;

#pragma unroll
        for (int ks = 0; ks < 2; ks++) {
            // Hold all A frags (32 regs), stream B frags one j at a time.
            wmma::fragment<wmma::matrix_a, 16, 16, 16, __nv_bfloat16, wmma::row_major> aH[4], aL[4];
#pragma unroll
            for (int i = 0; i < 4; i++) {
                const int ro = (wm * 64 + i * 16) * LDSR + ks * 16;
                wmma::load_matrix_sync(aH[i], sAh + ro, LDSR);
                wmma::load_matrix_sync(aL[i], sAl + ro, LDSR);
            }
#pragma unroll
            for (int j = 0; j < 2; j++) {
                wmma::fragment<wmma::matrix_b, 16, 16, 16, __nv_bfloat16, wmma::col_major> bH, bL;
                const int ro = (wn * 32 + j * 16) * LDSR + ks * 16;
                wmma::load_matrix_sync(bH, sWh + ro, LDSR);
                wmma::load_matrix_sync(bL, sWl + ro, LDSR);
#pragma unroll
                for (int i = 0; i < 4; i++) {
                    wmma::mma_sync(acc[i][j], aH[i], bH, acc[i][j]);
                    wmma::mma_sync(acc[i][j], aH[i], bL, acc[i][j]);
                    wmma::mma_sync(acc[i][j], aL[i], bH, acc[i][j]);
                }
            }
        }
        __syncthreads();
    }

    // ------------------------- epilogue ------------------------------------
    float* fb = (float*)smem;   // 128 x FB_LD fp32 (67.6 KB < 80 KB)
#pragma unroll
    for (int i = 0; i < 4; i++)
#pragma unroll
        for (int j = 0; j < 2; j++)
            wmma::store_matrix_sync(fb + (wm * 64 + i * 16) * FB_LD + wn * 32 + j * 16,
                                    acc[i][j], FB_LD, wmma::mem_row_major);
    __syncthreads();

    const float* zb = z + (size_t)m0 * NH + n0;
    float* ob = out + (size_t)m0 * (4 * NH) + n0;
    char* nxH = g_ahi[abuf ^ 1];
    char* nxL = g_alo[abuf ^ 1];

#pragma unroll
    for (int it = 0; it < 16; it++) {
        int idx4 = tid + it * 256;            // 0..4095 float4 slots
        int row  = idx4 >> 5;                 // 0..127
        int c4   = (idx4 & 31) << 2;          // 0..124

        float4 a  = *(float4*)&fb[row * FB_LD + c4];
        float4 zv = *(const float4*)(zb + (size_t)row * NH + c4);
        float4 mv = *(const float4*)(mu + n0 + c4);
        float4 sv = *(const float4*)(sig + n0 + c4);

        float v0 = fmaxf(a.x + __expf(fmaf(sv.x, zv.x, mv.x)), 0.0f);
        float v1 = fmaxf(a.y + __expf(fmaf(sv.y, zv.y, mv.y)), 0.0f);
        float v2 = fmaxf(a.z + __expf(fmaf(sv.z, zv.z, mv.z)), 0.0f);
        float v3 = fmaxf(a.w + __expf(fmaf(sv.w, zv.w, mv.w)), 0.0f);

        float4 o; o.x = v0; o.y = v1; o.z = v2; o.w = v3;
        *(float4*)(ob + (size_t)row * (4 * NH) + c4) = o;

        if (!last) {
            __nv_bfloat16 h0 = __float2bfloat16(v0), h1 = __float2bfloat16(v1);
            __nv_bfloat16 h2 = __float2bfloat16(v2), h3 = __float2bfloat16(v3);
            float l0 = v0 - __bfloat162float(h0), l1 = v1 - __bfloat162float(h1);
            float l2 = v2 - __bfloat162float(h2), l3 = v3 - __bfloat162float(h3);
            size_t off = ((size_t)(m0 + row) * NH + n0 + c4) * 2;  // bytes
            uint2 ph; ph.x = pack2(h0, h1); ph.y = pack2(h2, h3);
            uint2 pl; pl.x = pack2(__float2bfloat16(l0), __float2bfloat16(l1));
            pl.y = pack2(__float2bfloat16(l2), __float2bfloat16(l3));
            *(uint2*)(nxH + off) = ph;
            *(uint2*)(nxL + off) = pl;
        }
    }
}

// ---------------------------------------------------------------------------
// kernel_launch: prepasses + 4 chained fused GEMMs, graph-capturable.
// Inputs: x, weights, masks, mu, sigma, z. Output float32 [B, 4H].
// ---------------------------------------------------------------------------
extern "C" void kernel_launch(void* const* d_in, const int* in_sizes, int n_in,
                              void* d_out, int out_size) {
    const float* x   = (const float*)d_in[0];
    const float* w   = (const float*)d_in[1];
    const float* mk  = (const float*)d_in[2];
    const float* mu  = (const float*)d_in[3];
    const float* sg  = (const float*)d_in[4];
    const float* z   = (const float*)d_in[5];
    float*       out = (float*)d_out;

    cudaFuncSetAttribute(gemm_tc_kernel,
                         cudaFuncAttributeMaxDynamicSharedMemorySize, SMEM_BYTES);

    {   // W split
        unsigned blocks = (unsigned)(((size_t)NL * NH * NH / 2) / 256);
        wsplit_kernel<<<blocks, 256>>>(w, mk);
    }
    {   // x split
        unsigned blocks = (unsigned)(((size_t)NB * NH / 2) / 256);
        xsplit_kernel<<<blocks, 256>>>(x);
    }

    dim3 grid(NH / BN, NB / BM);  // (32, 32)
    for (int l = 0; l < NL; l++) {
        gemm_tc_kernel<<<grid, 256, SMEM_BYTES>>>(
            l, l & 1, (l == NL - 1) ? 1 : 0,
            z + (size_t)l * NB * NH,
            mu + (size_t)l * NH,
            sg + (size_t)l * NH,
            out + (size_t)l * NH);
    }
}